// round 3
// baseline (speedup 1.0000x reference)
#include <cuda_runtime.h>
#include <math.h>

#define Bb      128
#define Ll      2048
#define NOBS    32
#define NHID    512
#define NSTEPS  (Ll - 1)          // 2047
#define NCTA    128
#define NTHREADS 128
#define NBARS   (NSTEPS - 1)
#define BARMOD  ((unsigned long long)NBARS * NCTA)

// SMEM layout
#define AD_STRIDE 514                      // u64 per A-dup row (512 + 2 pad)
#define AD_U64    (32 * AD_STRIDE)         // 16448 u64 = 131584 B
#define SX_STRIDE 10                       // u64 per state row (8 pairs + 2 pad)
#define SX_U64    (NHID * SX_STRIDE)       // 5120 u64 = 40960 B
#define SMEM_BYTES ((AD_U64 + SX_U64) * 8) // 172544 B

__device__ float g_state[2][Bb * NHID];
__device__ unsigned long long g_count;

// ---------------------------------------------------------------------------
typedef unsigned long long u64;

__device__ __forceinline__ u64 pack2(float a, float b) {
    u64 r;
    asm("mov.b64 %0, {%1, %2};" : "=l"(r) : "f"(a), "f"(b));
    return r;
}
__device__ __forceinline__ void unpack2(u64 v, float& a, float& b) {
    asm("mov.b64 {%0, %1}, %2;" : "=f"(a), "=f"(b) : "l"(v));
}
// per-lane IEEE fma: acc.x = fma(a.x, x.x, acc.x), acc.y = fma(a.y, x.y, acc.y)
__device__ __forceinline__ void ffma2(u64& acc, u64 a, u64 x) {
    asm("fma.rn.f32x2 %0, %1, %2, %0;" : "+l"(acc) : "l"(a), "l"(x));
}

// XLA EmitFastTanh (with_fma path): clamp +-7.99881172180175781,
// FMA-contracted Horner in x^2, fp32 divide, |x|<0.0004 -> x.
__device__ __forceinline__ float tanh_xla(float x) {
    const float kClamp = 7.99881172180175781f;
    float xc = fminf(fmaxf(x, -kClamp), kClamp);
    float x2 = __fmul_rn(xc, xc);
    float num = -2.76076847742355e-16f;
    num = fmaf(x2, num, 2.00018790482477e-13f);
    num = fmaf(x2, num, -8.60467152213735e-11f);
    num = fmaf(x2, num, 5.12229709037114e-08f);
    num = fmaf(x2, num, 1.48572235717979e-05f);
    num = fmaf(x2, num, 6.37261928875436e-04f);
    num = fmaf(x2, num, 4.89352455891786e-03f);
    num = __fmul_rn(xc, num);
    float den = 1.19825839466702e-06f;
    den = fmaf(x2, den, 1.18534705686654e-04f);
    den = fmaf(x2, den, 2.26843463243900e-03f);
    den = fmaf(x2, den, 4.89352518554385e-03f);
    float r = __fdiv_rn(num, den);
    return (fabsf(x) < 0.0004f) ? x : r;
}

__device__ __forceinline__ void grid_barrier(u64 target) {
    __syncthreads();
    if (threadIdx.x == 0) {
        __threadfence();
        atomicAdd(&g_count, 1ULL);
        u64 v;
        do {
            asm volatile("ld.global.acquire.gpu.u64 %0, [%1];"
                         : "=l"(v) : "l"(&g_count));
        } while (v < target);
    }
    __syncthreads();
}

// ---------------------------------------------------------------------------
// Persistent HCNN scan, order-exact fp32.
// 128 CTAs = 16 n-tiles (32 cols) x 8 m-tiles (16 batches = 8 pairs).
// 128 threads: tx = column lane (0..31), ty = warp (0..3) -> pairs 2ty, 2ty+1.
// Each f32x2 lane carries a full ascending-k 512-FMA chain (single acc).
// ---------------------------------------------------------------------------
__global__ void __launch_bounds__(NTHREADS, 1) ptf_persistent(
    const float* __restrict__ data,   // [B, L, NOBS]
    const float* __restrict__ Amat,   // [NHID, NHID]
    const float* __restrict__ h0,     // [NHID]
    float* __restrict__ exps,
    float* __restrict__ states,
    float* __restrict__ deltas,
    float* __restrict__ partials)
{
    extern __shared__ u64 smem[];
    u64* sAd = smem;                  // [32][AD_STRIDE] : (a,a) dup pairs
    u64* sx  = smem + AD_U64;         // [512][SX_STRIDE] : 8 (vA,vB) pairs per k

    const int tid = threadIdx.x;
    const int tx  = tid & 31;
    const int ty  = tid >> 5;                 // 0..3
    const int nt  = blockIdx.x & 15;
    const int mt  = blockIdx.x >> 4;
    const int n0  = nt * 32;
    const int m0  = mt * 16;
    const int n   = n0 + tx;

    // ---- one-time: A rows n0..n0+31 -> SMEM, duplicated (a,a) ----
    for (int i = tid; i < 32 * 128; i += NTHREADS) {      // 4096 float4 chunks
        int nl = i >> 7;
        int kq = (i & 127) * 4;
        float4 a = *(const float4*)&Amat[(size_t)(n0 + nl) * NHID + kq];
        u64* dst = &sAd[(size_t)nl * AD_STRIDE + kq];
        dst[0] = pack2(a.x, a.x);
        dst[1] = pack2(a.y, a.y);
        dst[2] = pack2(a.z, a.z);
        dst[3] = pack2(a.w, a.w);
    }

    // ---- barrier base (monotonic counter across graph replays) ----
    u64 base;
    {
        u64 v;
        asm volatile("ld.global.acquire.gpu.u64 %0, [%1];" : "=l"(v) : "l"(&g_count));
        base = v - (v % BARMOD);
    }
    __syncthreads();   // A staging complete

    for (int t = 0; t < NSTEPS; t++) {
        const int rb = t & 1;
        const float* __restrict__ st_rd = g_state[rb];

        // -------- stage state pairs (+ exact injection + obs outputs) -------
        // unit (r, tid): pair p = r, k-quad = tid
        #pragma unroll
        for (int r = 0; r < 8; r++) {
            const int p  = r;
            const int k0 = tid * 4;
            const int bA = m0 + p;
            const int bB = bA + 8;
            const float* srcA = (t == 0) ? (h0 + k0) : (st_rd + (size_t)bA * NHID + k0);
            const float* srcB = (t == 0) ? (h0 + k0) : (st_rd + (size_t)bB * NHID + k0);
            float4 a4 = *(const float4*)srcA;
            float4 b4 = *(const float4*)srcB;

            if (t == 0 && nt == 0) {          // states[:,0,:] = s0 (pre-inject)
                *(float4*)&states[(size_t)bA * Ll * NHID + k0] = a4;
                *(float4*)&states[(size_t)bB * Ll * NHID + k0] = b4;
            }
            if (k0 < NOBS) {                  // teacher forcing: s + (y - s)
                float4 yA = *(const float4*)&data[((size_t)bA * Ll + t) * NOBS + k0];
                float4 yB = *(const float4*)&data[((size_t)bB * Ll + t) * NOBS + k0];
                float4 dA, dB;
                dA.x = __fsub_rn(yA.x, a4.x); dA.y = __fsub_rn(yA.y, a4.y);
                dA.z = __fsub_rn(yA.z, a4.z); dA.w = __fsub_rn(yA.w, a4.w);
                dB.x = __fsub_rn(yB.x, b4.x); dB.y = __fsub_rn(yB.y, b4.y);
                dB.z = __fsub_rn(yB.z, b4.z); dB.w = __fsub_rn(yB.w, b4.w);
                if (nt == 0) {
                    size_t oA = ((size_t)bA * Ll + t) * NOBS + k0;
                    size_t oB = ((size_t)bB * Ll + t) * NOBS + k0;
                    *(float4*)&exps[oA] = a4;  *(float4*)&exps[oB] = b4;
                    *(float4*)&deltas[oA]   = dA; *(float4*)&deltas[oB]   = dB;
                    *(float4*)&partials[oA] = dA; *(float4*)&partials[oB] = dB;
                }
                a4.x = __fadd_rn(a4.x, dA.x); a4.y = __fadd_rn(a4.y, dA.y);
                a4.z = __fadd_rn(a4.z, dA.z); a4.w = __fadd_rn(a4.w, dA.w);
                b4.x = __fadd_rn(b4.x, dB.x); b4.y = __fadd_rn(b4.y, dB.y);
                b4.z = __fadd_rn(b4.z, dB.z); b4.w = __fadd_rn(b4.w, dB.w);
            }
            sx[(size_t)(k0 + 0) * SX_STRIDE + p] = pack2(a4.x, b4.x);
            sx[(size_t)(k0 + 1) * SX_STRIDE + p] = pack2(a4.y, b4.y);
            sx[(size_t)(k0 + 2) * SX_STRIDE + p] = pack2(a4.z, b4.z);
            sx[(size_t)(k0 + 3) * SX_STRIDE + p] = pack2(a4.w, b4.w);
        }
        __syncthreads();

        // -------- compute: two full ascending-k chains per thread ----------
        u64 acc0 = 0, acc1 = 0;               // pairs 2ty, 2ty+1  (both lanes 0.0f)
        const u64* arow = &sAd[(size_t)tx * AD_STRIDE];
        const int  poff = 2 * ty;
        #pragma unroll 4
        for (int k = 0; k < NHID; k += 2) {
            ulonglong2 ad = *(const ulonglong2*)&arow[k];            // (a_k,a_k),(a_k1,a_k1)
            ulonglong2 x0 = *(const ulonglong2*)&sx[(size_t)k * SX_STRIDE + poff];
            ulonglong2 x1 = *(const ulonglong2*)&sx[(size_t)(k + 1) * SX_STRIDE + poff];
            ffma2(acc0, ad.x, x0.x);
            ffma2(acc1, ad.x, x0.y);
            ffma2(acc0, ad.y, x1.x);
            ffma2(acc1, ad.y, x1.y);
        }

        // -------- tanh + writes --------------------------------------------
        float z0a, z0b, z1a, z1b;
        unpack2(acc0, z0a, z0b);
        unpack2(acc1, z1a, z1b);
        const int b0 = m0 + 2 * ty;           // pair0 -> (b0, b0+8)
        const int b1 = b0 + 1;                // pair1 -> (b1, b1+8)
        float h0a = tanh_xla(z0a);
        float h0b = tanh_xla(z0b);
        float h1a = tanh_xla(z1a);
        float h1b = tanh_xla(z1b);

        const int wb = rb ^ 1;
        g_state[wb][(size_t)b0 * NHID + n]       = h0a;
        g_state[wb][(size_t)(b0 + 8) * NHID + n] = h0b;
        g_state[wb][(size_t)b1 * NHID + n]       = h1a;
        g_state[wb][(size_t)(b1 + 8) * NHID + n] = h1b;
        states[((size_t)b0 * Ll + t + 1) * NHID + n]       = h0a;
        states[((size_t)(b0 + 8) * Ll + t + 1) * NHID + n] = h0b;
        states[((size_t)b1 * Ll + t + 1) * NHID + n]       = h1a;
        states[((size_t)(b1 + 8) * Ll + t + 1) * NHID + n] = h1b;

        if (t == NSTEPS - 1 && nt == 0) {
            // last_y_hat = s_L[:, :32]; delta uses data[:, L-2] (reference quirk)
            const int bs[4]  = {b0, b0 + 8, b1, b1 + 8};
            const float hs[4] = {h0a, h0b, h1a, h1b};
            #pragma unroll
            for (int i = 0; i < 4; i++) {
                size_t o = ((size_t)bs[i] * Ll + (Ll - 1)) * NOBS + tx;
                exps[o] = hs[i];
                float d = __fsub_rn(data[((size_t)bs[i] * Ll + (Ll - 2)) * NOBS + tx],
                                    hs[i]);
                deltas[o]   = d;
                partials[o] = d;
            }
        }

        if (t < NSTEPS - 1)
            grid_barrier(base + (u64)(t + 1) * NCTA);
    }
}

// ---------------------------------------------------------------------------
extern "C" void kernel_launch(void* const* d_in, const int* in_sizes, int n_in,
                              void* d_out, int out_size) {
    const float* data = (const float*)d_in[0];  // [128,2048,32]
    const float* A    = (const float*)d_in[1];  // [512,512]
    const float* h0   = (const float*)d_in[2];  // [1,512]
    // d_in[3] = prob (0) -> dropout identity

    float* out      = (float*)d_out;
    float* exps     = out;
    float* states   = exps   + (size_t)Bb * Ll * NOBS;
    float* deltas   = states + (size_t)Bb * Ll * NHID;
    float* partials = deltas + (size_t)Bb * Ll * NOBS;

    cudaFuncSetAttribute(ptf_persistent,
                         cudaFuncAttributeMaxDynamicSharedMemorySize, SMEM_BYTES);
    ptf_persistent<<<NCTA, NTHREADS, SMEM_BYTES>>>(data, A, h0,
                                                   exps, states, deltas, partials);
}